// round 6
// baseline (speedup 1.0000x reference)
#include <cuda_runtime.h>
#include <float.h>

// ROI max pool, four-phase, load-balanced:
//  1) transpose features [2,256,50,50] -> channel-last g_feat_t [2,50,50,256]
//  2) prep: per-(roi,bin) bounds {flat_start, rows, wm1} -> g_meta (6272 int4)
//  3) pool: warp = one bin x 128 channels; 64-thread blocks (100% occ,
//     fine-grained balance); writes bin-major g_tmp[n][ij][c] coalesced
//  4) reshape: g_tmp[n][ij][c] -> out[n][c][ij] via smem tiles, coalesced

#define OUTP 7
#define NBINS 49
#define CCH  256
#define HH   50
#define WW   50
#define HWSZ (HH * WW)
#define BB   2
#define CS   (CCH / 4)          // float4 stride between spatial positions

__device__ __align__(16) float g_feat_t[BB * HWSZ * CCH];      // 5.12 MB
__device__ __align__(16) float g_tmp[128 * NBINS * CCH];        // 6.42 MB
__device__ int4 g_meta[128 * NBINS];                            // 100 KB

// ---------------- 1) transpose: [b][c][hw] -> [b][hw][c] ----------------
__global__ void transpose_kernel(const float* __restrict__ feat)
{
    __shared__ float tile[32][33];
    int b   = blockIdx.z;
    int hw0 = blockIdx.x * 32;
    int c0  = blockIdx.y * 32;

    int hw_r = hw0 + threadIdx.x;
    #pragma unroll
    for (int r = threadIdx.y; r < 32; r += 8) {
        if (hw_r < HWSZ)
            tile[r][threadIdx.x] = feat[((size_t)b * CCH + c0 + r) * HWSZ + hw_r];
    }
    __syncthreads();
    #pragma unroll
    for (int r = threadIdx.y; r < 32; r += 8) {
        int hw_w = hw0 + r;
        if (hw_w < HWSZ)
            g_feat_t[((size_t)b * HWSZ + hw_w) * CCH + c0 + threadIdx.x] =
                tile[threadIdx.x][r];
    }
}

// ---------------- 2) prep: bounds per (n, ij) ----------------
__global__ void prep_kernel(const float* __restrict__ rois)
{
    int t = blockIdx.x * blockDim.x + threadIdx.x;
    if (t >= 128 * NBINS) return;
    int n  = t / NBINS;
    int ij = t - n * NBINS;
    int i  = ij / OUTP;
    int j  = ij - i * OUTP;

    const float* r = rois + n * 5;
    int im = (int)rintf(r[0]);
    int x1 = (int)rintf(r[1] * 0.0625f);
    int y1 = (int)rintf(r[2] * 0.0625f);
    int x2 = (int)rintf(r[3] * 0.0625f);
    int y2 = (int)rintf(r[4] * 0.0625f);
    unsigned h = (unsigned)(y2 - y1 + 1);
    unsigned w = (unsigned)(x2 - x1 + 1);

    int ys = (int)((unsigned)(i * h) / 7u) + y1;
    int ye = (int)(((unsigned)((i + 1) * h) + 6u) / 7u) + y1;
    int xs = (int)((unsigned)(j * w) / 7u) + x1;
    int xe = (int)(((unsigned)((j + 1) * w) + 6u) / 7u) + x1;
    ye = min(ye, HH);  xe = min(xe, WW);   // safety (provably no-ops)

    int4 m;
    m.x = im * HWSZ + ys * WW + xs;   // flat spatial start
    m.y = ye - ys;                    // rows (>=1)
    m.z = xe - xs - 1;                // wm1 in [0,7]
    m.w = 0;
    g_meta[t] = m;
}

__device__ __forceinline__ float4 fmax4(float4 a, float4 b)
{
    return make_float4(fmaxf(a.x, b.x), fmaxf(a.y, b.y),
                       fmaxf(a.z, b.z), fmaxf(a.w, b.w));
}

// ---------------- 3) pool: grid (49, 128), block 64 = 2 warps ----------------
__global__ __launch_bounds__(64) void roi_pool_kernel(void)
{
    int ij   = blockIdx.x;
    int n    = blockIdx.y;
    int lane = threadIdx.x & 31;
    int cg   = threadIdx.x >> 5;      // 0/1: channels [cg*128, +128)

    int4 m = __ldg(&g_meta[n * NBINS + ij]);
    int wm1 = m.z;

    const float4* base = (const float4*)g_feat_t
                       + (size_t)m.x * CS + cg * 32 + lane;

    float4 acc = make_float4(-FLT_MAX, -FLT_MAX, -FLT_MAX, -FLT_MAX);
    for (int r = 0; r < m.y; ++r) {
        const float4* row = base + (size_t)r * (WW * CS);
        float4 v0 = __ldg(row);
        float4 v1 = __ldg(row + min(1, wm1) * CS);
        float4 v2 = __ldg(row + min(2, wm1) * CS);
        float4 v3 = __ldg(row + min(3, wm1) * CS);
        float4 m0 = fmax4(v0, v1);
        float4 m1 = fmax4(v2, v3);
        if (wm1 >= 4) {               // warp-uniform branch
            float4 v4 = __ldg(row + 4 * CS);
            float4 v5 = __ldg(row + min(5, wm1) * CS);
            float4 v6 = __ldg(row + min(6, wm1) * CS);
            float4 v7 = __ldg(row + min(7, wm1) * CS);
            m0 = fmax4(m0, fmax4(v4, v5));
            m1 = fmax4(m1, fmax4(v6, v7));
        }
        acc = fmax4(acc, fmax4(m0, m1));
    }

    // bin-major scratch: g_tmp[n][ij][c], warp writes 128 contiguous ch
    ((float4*)g_tmp)[((size_t)n * NBINS + ij) * (CCH / 4) + cg * 32 + lane] = acc;
}

// ---------------- 4) reshape: g_tmp[n][ij][c] -> out[n][c][ij] ----------------
// grid (4, 128): 64-channel slab per block; block 256 threads
__global__ __launch_bounds__(256) void reshape_kernel(float* __restrict__ out)
{
    __shared__ float s[NBINS][65];
    int c0 = blockIdx.x * 64;
    int n  = blockIdx.y;

    const float* src = g_tmp + (size_t)n * NBINS * CCH + c0;
    for (int p = threadIdx.x; p < NBINS * 64; p += 256) {
        int ij = p >> 6;
        int cl = p & 63;
        s[ij][cl] = src[(size_t)ij * CCH + cl];
    }
    __syncthreads();

    float* dst = out + ((size_t)n * CCH + c0) * NBINS;
    for (int p = threadIdx.x; p < 64 * NBINS; p += 256) {
        int cl = p / NBINS;
        int ij = p - cl * NBINS;
        dst[p] = s[ij][cl];
    }
}

extern "C" void kernel_launch(void* const* d_in, const int* in_sizes, int n_in,
                              void* d_out, int out_size)
{
    const float* feat = (const float*)d_in[0];
    const float* rois = (const float*)d_in[1];
    float* out = (float*)d_out;

    dim3 tgrid((HWSZ + 31) / 32, CCH / 32, BB);
    transpose_kernel<<<tgrid, dim3(32, 8)>>>(feat);

    prep_kernel<<<(128 * NBINS + 255) / 256, 256>>>(rois);

    roi_pool_kernel<<<dim3(NBINS, 128), 64>>>();

    reshape_kernel<<<dim3(4, 128), 256>>>(out);
}

// round 7
// speedup vs baseline: 1.1322x; 1.1322x over previous
#include <cuda_runtime.h>
#include <float.h>

// ROI max pool, three-phase:
//  1) transpose features [2,256,50,50] -> channel-last g_feat_t [2,50,50,256]
//  2) prep: per-(roi,bin) bounds {flat_start, rows, wm1} -> g_meta
//  3) pool: block = (roi n, output row i); 14 warps = 7 j-bins x 2 ch-groups,
//     one task per warp (balanced). Unrolled width<=8 inner loop (high MLP).
//     Results staged in smem, written straight to out (no scratch, no
//     reshape kernel).

#define OUTP 7
#define NBINS 49
#define CCH  256
#define HH   50
#define WW   50
#define HWSZ (HH * WW)
#define BB   2
#define CS   (CCH / 4)          // float4 stride between spatial positions

__device__ __align__(16) float g_feat_t[BB * HWSZ * CCH];   // 5.12 MB
__device__ int4 g_meta[128 * NBINS];                        // 100 KB

// ---------------- 1) transpose: [b][c][hw] -> [b][hw][c] ----------------
__global__ void transpose_kernel(const float* __restrict__ feat)
{
    __shared__ float tile[32][33];
    int b   = blockIdx.z;
    int hw0 = blockIdx.x * 32;
    int c0  = blockIdx.y * 32;

    int hw_r = hw0 + threadIdx.x;
    #pragma unroll
    for (int r = threadIdx.y; r < 32; r += 8) {
        if (hw_r < HWSZ)
            tile[r][threadIdx.x] = feat[((size_t)b * CCH + c0 + r) * HWSZ + hw_r];
    }
    __syncthreads();
    #pragma unroll
    for (int r = threadIdx.y; r < 32; r += 8) {
        int hw_w = hw0 + r;
        if (hw_w < HWSZ)
            g_feat_t[((size_t)b * HWSZ + hw_w) * CCH + c0 + threadIdx.x] =
                tile[threadIdx.x][r];
    }
}

// ---------------- 2) prep: bounds per (n, ij) ----------------
__global__ void prep_kernel(const float* __restrict__ rois)
{
    int t = blockIdx.x * blockDim.x + threadIdx.x;
    if (t >= 128 * NBINS) return;
    int n  = t / NBINS;
    int ij = t - n * NBINS;
    int i  = ij / OUTP;
    int j  = ij - i * OUTP;

    const float* r = rois + n * 5;
    int im = (int)rintf(r[0]);
    int x1 = (int)rintf(r[1] * 0.0625f);
    int y1 = (int)rintf(r[2] * 0.0625f);
    int x2 = (int)rintf(r[3] * 0.0625f);
    int y2 = (int)rintf(r[4] * 0.0625f);
    unsigned h = (unsigned)(y2 - y1 + 1);
    unsigned w = (unsigned)(x2 - x1 + 1);

    int ys = (int)((unsigned)(i * h) / 7u) + y1;
    int ye = (int)(((unsigned)((i + 1) * h) + 6u) / 7u) + y1;
    int xs = (int)((unsigned)(j * w) / 7u) + x1;
    int xe = (int)(((unsigned)((j + 1) * w) + 6u) / 7u) + x1;
    ye = min(ye, HH);  xe = min(xe, WW);

    int4 m;
    m.x = im * HWSZ + ys * WW + xs;   // flat spatial start
    m.y = ye - ys;                    // rows (>=1)
    m.z = xe - xs - 1;                // wm1 in [0,7]
    m.w = 0;
    g_meta[t] = m;
}

__device__ __forceinline__ float4 fmax4(float4 a, float4 b)
{
    return make_float4(fmaxf(a.x, b.x), fmaxf(a.y, b.y),
                       fmaxf(a.z, b.z), fmaxf(a.w, b.w));
}

// ---------------- 3) pool: grid (7, 128), block 448 = 14 warps ----------------
#define SPITCH 260
__global__ __launch_bounds__(448) void roi_pool_kernel(float* __restrict__ out)
{
    __shared__ __align__(16) float s[OUTP * SPITCH];

    int i    = blockIdx.x;
    int n    = blockIdx.y;
    int lane = threadIdx.x & 31;
    int wrp  = threadIdx.x >> 5;      // 0..13
    int j    = wrp % OUTP;            // bin column
    int cg   = wrp / OUTP;            // 0/1: channels [cg*128, +128)

    int4 m = __ldg(&g_meta[n * NBINS + i * OUTP + j]);
    int wm1 = m.z;

    const float4* base = (const float4*)g_feat_t
                       + (size_t)m.x * CS + cg * 32 + lane;

    float4 acc = make_float4(-FLT_MAX, -FLT_MAX, -FLT_MAX, -FLT_MAX);
    for (int r = 0; r < m.y; ++r) {
        const float4* row = base + (size_t)r * (WW * CS);
        float4 v0 = __ldg(row);
        float4 v1 = __ldg(row + min(1, wm1) * CS);
        float4 v2 = __ldg(row + min(2, wm1) * CS);
        float4 v3 = __ldg(row + min(3, wm1) * CS);
        float4 m0 = fmax4(v0, v1);
        float4 m1 = fmax4(v2, v3);
        if (wm1 >= 4) {               // warp-uniform branch
            float4 v4 = __ldg(row + 4 * CS);
            float4 v5 = __ldg(row + min(5, wm1) * CS);
            float4 v6 = __ldg(row + min(6, wm1) * CS);
            float4 v7 = __ldg(row + min(7, wm1) * CS);
            m0 = fmax4(m0, fmax4(v4, v5));
            m1 = fmax4(m1, fmax4(v6, v7));
        }
        acc = fmax4(acc, fmax4(m0, m1));
    }

    // stage: s[j][cg*128 + lane*4 .. +4], conflict-free float4 store
    *(float4*)&s[j * SPITCH + cg * 128 + lane * 4] = acc;
    __syncthreads();

    // out[n][c][i*7+j]: 256 runs of 7 contiguous floats; 1792 floats,
    // 448 threads x 4 iterations, near-coalesced.
    float* dst = out + (size_t)n * CCH * NBINS + i * OUTP;
    #pragma unroll
    for (int p = threadIdx.x; p < CCH * OUTP; p += 448) {
        int c  = p / OUTP;
        int jj = p - c * OUTP;
        dst[(size_t)c * NBINS + jj] = s[jj * SPITCH + c];
    }
}

extern "C" void kernel_launch(void* const* d_in, const int* in_sizes, int n_in,
                              void* d_out, int out_size)
{
    const float* feat = (const float*)d_in[0];
    const float* rois = (const float*)d_in[1];
    float* out = (float*)d_out;

    dim3 tgrid((HWSZ + 31) / 32, CCH / 32, BB);
    transpose_kernel<<<tgrid, dim3(32, 8)>>>(feat);

    prep_kernel<<<(128 * NBINS + 255) / 256, 256>>>(rois);

    roi_pool_kernel<<<dim3(OUTP, 128), 448>>>(out);
}

// round 8
// speedup vs baseline: 1.2133x; 1.0717x over previous
#include <cuda_runtime.h>
#include <float.h>

// ROI max pool, two kernels:
//  1) transpose features [2,256,50,50] -> channel-last g_feat_t [2,50,50,256]
//     float4-vectorized on BOTH global sides (smem 32x33 tile, conflict-free)
//  2) pool: block = (roi n, output row i); 14 warps = 7 j-bins x 2 ch-groups,
//     one bin x 128 channels per warp; bounds computed inline (no prep pass);
//     width<=8 fully unrolled with clamped loads (high MLP); smem-staged
//     coalesced output.

#define OUTP 7
#define NBINS 49
#define CCH  256
#define HH   50
#define WW   50
#define HWSZ (HH * WW)
#define BB   2
#define CS   (CCH / 4)          // float4 stride between spatial positions

__device__ __align__(16) float g_feat_t[BB * HWSZ * CCH];   // 5.12 MB

// ---------------- 1) transpose: [b][c][hw] -> [b][hw][c], vectorized ------
__global__ __launch_bounds__(256) void transpose_kernel(const float* __restrict__ feat)
{
    __shared__ float tile[32][33];
    int b   = blockIdx.z;
    int hw0 = blockIdx.x * 32;
    int c0  = blockIdx.y * 32;
    int t   = threadIdx.x;

    // read: thread = (channel row cl, float4 along hw)
    {
        int cl = t >> 3;            // 0..31
        int h4 = (t & 7) * 4;       // 0,4,...,28
        int hw = hw0 + h4;
        if (hw < HWSZ) {
            float4 v = __ldg((const float4*)
                (feat + ((size_t)b * CCH + c0 + cl) * HWSZ + hw));
            tile[cl][h4 + 0] = v.x;
            tile[cl][h4 + 1] = v.y;
            tile[cl][h4 + 2] = v.z;
            tile[cl][h4 + 3] = v.w;
        }
    }
    __syncthreads();
    // write: thread = (hw row, float4 along channels)
    {
        int hwl = t >> 3;           // 0..31
        int c4  = (t & 7) * 4;      // 0,4,...,28
        int hw  = hw0 + hwl;
        if (hw < HWSZ) {
            float4 o;
            o.x = tile[c4 + 0][hwl];
            o.y = tile[c4 + 1][hwl];
            o.z = tile[c4 + 2][hwl];
            o.w = tile[c4 + 3][hwl];
            *(float4*)(g_feat_t + ((size_t)b * HWSZ + hw) * CCH + c0 + c4) = o;
        }
    }
}

__device__ __forceinline__ float4 fmax4(float4 a, float4 b)
{
    return make_float4(fmaxf(a.x, b.x), fmaxf(a.y, b.y),
                       fmaxf(a.z, b.z), fmaxf(a.w, b.w));
}

// ---------------- 2) pool: grid (7, 128), block 448 = 14 warps -------------
#define SPITCH 260
__global__ __launch_bounds__(448) void roi_pool_kernel(
    const float* __restrict__ rois, float* __restrict__ out)
{
    __shared__ __align__(16) float s[OUTP * SPITCH];

    int i    = blockIdx.x;
    int n    = blockIdx.y;
    int lane = threadIdx.x & 31;
    int wrp  = threadIdx.x >> 5;      // 0..13
    int j    = wrp % OUTP;            // bin column
    int cg   = wrp / OUTP;            // 0/1: channels [cg*128, +128)

    // inline bounds (uniform across warp; ~30 ALU ops amortized over 128 ch)
    const float* r = rois + n * 5;
    int im = (int)rintf(__ldg(r + 0));
    int x1 = (int)rintf(__ldg(r + 1) * 0.0625f);
    int y1 = (int)rintf(__ldg(r + 2) * 0.0625f);
    int x2 = (int)rintf(__ldg(r + 3) * 0.0625f);
    int y2 = (int)rintf(__ldg(r + 4) * 0.0625f);
    unsigned h = (unsigned)(y2 - y1 + 1);
    unsigned w = (unsigned)(x2 - x1 + 1);

    int ys = (int)((unsigned)(i * h) / 7u) + y1;
    int ye = (int)(((unsigned)((i + 1) * h) + 6u) / 7u) + y1;
    int xs = (int)((unsigned)(j * w) / 7u) + x1;
    int xe = (int)(((unsigned)((j + 1) * w) + 6u) / 7u) + x1;
    ye = min(ye, HH);  xe = min(xe, WW);

    int rows = ye - ys;               // >= 1
    int wm1  = xe - xs - 1;           // 0..7

    const float4* base = (const float4*)g_feat_t
        + ((size_t)(im * HWSZ + ys * WW + xs)) * CS + cg * 32 + lane;

    float4 acc = make_float4(-FLT_MAX, -FLT_MAX, -FLT_MAX, -FLT_MAX);
    for (int rr = 0; rr < rows; ++rr) {
        const float4* row = base + (size_t)rr * (WW * CS);
        float4 v0 = __ldg(row);
        float4 v1 = __ldg(row + min(1, wm1) * CS);
        float4 v2 = __ldg(row + min(2, wm1) * CS);
        float4 v3 = __ldg(row + min(3, wm1) * CS);
        float4 m0 = fmax4(v0, v1);
        float4 m1 = fmax4(v2, v3);
        if (wm1 >= 4) {               // warp-uniform branch
            float4 v4 = __ldg(row + 4 * CS);
            float4 v5 = __ldg(row + min(5, wm1) * CS);
            float4 v6 = __ldg(row + min(6, wm1) * CS);
            float4 v7 = __ldg(row + min(7, wm1) * CS);
            m0 = fmax4(m0, fmax4(v4, v5));
            m1 = fmax4(m1, fmax4(v6, v7));
        }
        acc = fmax4(acc, fmax4(m0, m1));
    }

    *(float4*)&s[j * SPITCH + cg * 128 + lane * 4] = acc;
    __syncthreads();

    // out[n][c][i*7+j]: 256 runs of 7 contiguous floats.
    float* dst = out + (size_t)n * CCH * NBINS + i * OUTP;
    #pragma unroll
    for (int p = threadIdx.x; p < CCH * OUTP; p += 448) {
        int c  = p / OUTP;
        int jj = p - c * OUTP;
        dst[(size_t)c * NBINS + jj] = s[jj * SPITCH + c];
    }
}

extern "C" void kernel_launch(void* const* d_in, const int* in_sizes, int n_in,
                              void* d_out, int out_size)
{
    const float* feat = (const float*)d_in[0];
    const float* rois = (const float*)d_in[1];
    float* out = (float*)d_out;

    dim3 tgrid((HWSZ + 31) / 32, CCH / 32, BB);   // 79 x 8 x 2
    transpose_kernel<<<tgrid, 256>>>(feat);

    roi_pool_kernel<<<dim3(OUTP, 128), 448>>>(rois, out);
}